// round 8
// baseline (speedup 1.0000x reference)
#include <cuda_runtime.h>
#include <math.h>
#include <stdint.h>

// ---------------------------------------------------------------------------
// ImportanceRenderer: tf32-MMA MLP + smem-param gather.
//  K0: transpose planes (B,3,32,256,256) -> channel-last
//  K1: coarse eval (gather + tf32 MMA MLP) + fused importance sampling
//  K2: fine eval + fused merge + final 96-sample ray march
// Block = 192 threads = 6 warps = 4 rays x 48 samples (rows 0..191 = samples).
// ---------------------------------------------------------------------------

#define B_N 2
#define R_N 4096
#define SC 48
#define SF 48
#define NRAY (B_N * R_N)        // 8192
#define NSAMP (NRAY * SC)       // 393216
#define CPL 32
#define HPX 256
#define HID 64
#define CRGB 32
#define PLSTRIDE (HPX * HPX * CPL)

#define RAY_START_F 2.25f
#define DELTA_F (1.05f / 47.0f)

#define OFF_DEPTH (NRAY * CRGB)         // 262144
#define OFF_WSUM  (OFF_DEPTH + NRAY)    // 270336
#define OFF_SDF   (OFF_WSUM + NRAY)     // 278528

#define BUFS 68   // s_buf row stride in floats (68 % 32 == 4 -> conflict-free frags)

// Dynamic smem layout (float offsets)
#define SM_BUF   0
#define SM_GP    (192 * BUFS)              // 13056 : gather params 192*24
#define SM_W1F   (SM_GP + 192 * 24)        // 17664 : w1 frags hi(2048)+lo(2048)
#define SM_W2F   (SM_W1F + 4096)           // 21760 : w2 frags hi(2560)+lo(2560)
#define SM_B1    (SM_W2F + 5120)           // 26880
#define SM_B2    (SM_B1 + 64)              // 26944 (40 floats)
#define SM_SIG   (SM_B2 + 40)              // 26984
#define SM_Z     (SM_SIG + 192)            // 27176
#define SM_TOTALF (SM_Z + 192)             // 27368 floats = 109472 bytes

// Static scratch
__device__ float g_planesT[6 * PLSTRIDE];           // 50.3 MB
__device__ float g_rgb_c[(size_t)NSAMP * CRGB];     // 50.3 MB
__device__ float g_zf[NSAMP];

__device__ __forceinline__ float softplus_f(float x) {
    return fmaxf(x, 0.f) + __logf(1.f + __expf(-fabsf(x)));
}
__device__ __forceinline__ float sigmoid_f(float x) {
    return 1.f / (1.f + __expf(-x));
}
__device__ __forceinline__ float zc_depth(int i) {
    return RAY_START_F + ((float)i + 0.5f) * DELTA_F;
}
__device__ __forceinline__ unsigned f2tf(float f) {
    unsigned u;
    asm("cvt.rna.tf32.f32 %0, %1;" : "=r"(u) : "f"(f));
    return u;
}
__device__ __forceinline__ void split_tf(float v, unsigned& hi, unsigned& lo) {
    hi = f2tf(v);
    lo = f2tf(v - __uint_as_float(hi));
}
__device__ __forceinline__ void mma8(float c[4], const unsigned a[4],
                                     unsigned b0, unsigned b1) {
    asm volatile(
        "mma.sync.aligned.m16n8k8.row.col.f32.tf32.tf32.f32 "
        "{%0,%1,%2,%3}, {%4,%5,%6,%7}, {%8,%9}, {%0,%1,%2,%3};\n"
        : "+f"(c[0]), "+f"(c[1]), "+f"(c[2]), "+f"(c[3])
        : "r"(a[0]), "r"(a[1]), "r"(a[2]), "r"(a[3]), "r"(b0), "r"(b1));
}

// ---------------------------------------------------------------------------
// K0: tiled transpose per plane
// ---------------------------------------------------------------------------
__global__ void transpose_planes_kernel(const float* __restrict__ in) {
    __shared__ float tile[32][33];
    int p = blockIdx.y;
    int hw0 = blockIdx.x * 32;
    int tx = threadIdx.x, ty = threadIdx.y;
    const float* ip = in + (size_t)p * CPL * (HPX * HPX);
    float* op = g_planesT + (size_t)p * PLSTRIDE;
    #pragma unroll
    for (int c = ty; c < 32; c += 8)
        tile[c][tx] = ip[(size_t)c * (HPX * HPX) + hw0 + tx];
    __syncthreads();
    #pragma unroll
    for (int r = ty; r < 32; r += 8)
        op[(size_t)(hw0 + r) * 32 + tx] = tile[tx][r];
}

// ---------------------------------------------------------------------------
// K1/K2 fused eval
// ---------------------------------------------------------------------------
template <int PASS>
__global__ __launch_bounds__(192)
void eval_kernel(const float* __restrict__ origins,
                 const float* __restrict__ dirs,
                 const float* __restrict__ w1, const float* __restrict__ b1,
                 const float* __restrict__ w2, const float* __restrict__ b2,
                 float* __restrict__ out) {
    extern __shared__ float smem[];
    float* s_buf = smem + SM_BUF;
    float* s_gp  = smem + SM_GP;
    unsigned* w1f = reinterpret_cast<unsigned*>(smem + SM_W1F);
    unsigned* w2f = reinterpret_cast<unsigned*>(smem + SM_W2F);
    float* s_b1 = smem + SM_B1;
    float* s_b2 = smem + SM_B2;
    float* s_sig = smem + SM_SIG;
    float* s_z = smem + SM_Z;

    const int tid = threadIdx.x;
    const int lane = tid & 31;
    const int warp = tid >> 5;
    const int g = lane >> 2;      // fragment group (row / n index)
    const int t = lane & 3;       // fragment thread-in-group (k / col index)

    // ---- weight fragment setup (hi/lo tf32 split, fragment-order layout) ----
    // w1f: slot = nt*4+kt (nt<8, kt<4); entry pair at [slot*32+lane]*2
    for (int i = tid; i < 1024; i += 192) {
        int l = i & 31, slot = i >> 5;
        int kt = slot & 3, nt = slot >> 2;
        int k0 = kt * 8 + (l & 3), n = nt * 8 + (l >> 2);
        float v0 = w1[k0 * HID + n];
        float v1 = w1[(k0 + 4) * HID + n];
        unsigned h0, l0, h1, l1;
        split_tf(v0, h0, l0);
        split_tf(v1, h1, l1);
        w1f[i * 2 + 0] = h0; w1f[i * 2 + 1] = h1;
        w1f[2048 + i * 2 + 0] = l0; w1f[2048 + i * 2 + 1] = l1;
    }
    // w2f: slot = nt*8+kt (nt<5, kt<8)
    for (int i = tid; i < 1280; i += 192) {
        int l = i & 31, slot = i >> 5;
        int kt = slot & 7, nt = slot >> 3;
        int k0 = kt * 8 + (l & 3), n = nt * 8 + (l >> 2);
        float v0 = (n < 33) ? w2[k0 * 33 + n] : 0.f;
        float v1 = (n < 33) ? w2[(k0 + 4) * 33 + n] : 0.f;
        unsigned h0, l0, h1, l1;
        split_tf(v0, h0, l0);
        split_tf(v1, h1, l1);
        w2f[i * 2 + 0] = h0; w2f[i * 2 + 1] = h1;
        w2f[2560 + i * 2 + 0] = l0; w2f[2560 + i * 2 + 1] = l1;
    }
    if (tid < HID) s_b1[tid] = b1[tid];
    if (tid < 40) s_b2[tid] = (tid < 33) ? b2[tid] : 0.f;

    // ---- phase A: per-sample coordinates -> gather params in smem ----
    const int gs = blockIdx.x * 192 + tid;
    const int rayLocal = tid / 48;
    const int samp = tid - rayLocal * 48;
    const int ray = blockIdx.x * 4 + rayLocal;

    float tz;
    if (PASS == 0) tz = zc_depth(samp);
    else tz = __ldg(&g_zf[gs]);
    s_z[tid] = tz;

    {
        float ox = __ldg(&origins[ray * 3 + 0]);
        float oy = __ldg(&origins[ray * 3 + 1]);
        float oz = __ldg(&origins[ray * 3 + 2]);
        float dx = __ldg(&dirs[ray * 3 + 0]);
        float dy = __ldg(&dirs[ray * 3 + 1]);
        float dz = __ldg(&dirs[ray * 3 + 2]);
        float X = fmaf(tz, dx, ox), Y = fmaf(tz, dy, oy), Z = fmaf(tz, dz, oz);
        int bb = ray >> 12;
        #pragma unroll
        for (int p = 0; p < 3; p++) {
            float u = (p == 2) ? Z : X;
            float v = (p == 0) ? Y : (p == 1) ? Z : X;
            float x = fmaf(u, 128.f, 127.5f);
            float y = fmaf(v, 128.f, 127.5f);
            float x0f = floorf(x), y0f = floorf(y);
            float fx = x - x0f, fy = y - y0f;
            int xi0 = min(max((int)x0f, 0), 255);
            int xi1 = min(max((int)x0f + 1, 0), 255);
            int yi0 = min(max((int)y0f, 0), 255);
            int yi1 = min(max((int)y0f + 1, 0), 255);
            float wx0 = (x0f >= 0.f && x0f < 256.f) ? (1.f - fx) : 0.f;
            float wx1 = (x0f + 1.f >= 0.f && x0f + 1.f < 256.f) ? fx : 0.f;
            float wy0 = (y0f >= 0.f && y0f < 256.f) ? (1.f - fy) : 0.f;
            float wy1 = (y0f + 1.f >= 0.f && y0f + 1.f < 256.f) ? fy : 0.f;
            int base = (bb * 3 + p) * PLSTRIDE;
            int o0 = base + yi0 * (HPX * CPL);
            int o1 = base + yi1 * (HPX * CPL);
            float2* gp = reinterpret_cast<float2*>(s_gp + tid * 24 + p * 8);
            gp[0] = make_float2(__int_as_float(o0 + xi0 * CPL), wy0 * wx0);
            gp[1] = make_float2(__int_as_float(o0 + xi1 * CPL), wy0 * wx1);
            gp[2] = make_float2(__int_as_float(o1 + xi0 * CPL), wy1 * wx0);
            gp[3] = make_float2(__int_as_float(o1 + xi1 * CPL), wy1 * wx1);
        }
    }
    __syncthreads();

    // ---- gather: warp-cooperative, lane = corner(2b) x chunk(3b) ----
    {
        const int corner = lane >> 3;
        const int chunk = lane & 7;
        #pragma unroll 2
        for (int i = 0; i < 32; i++) {
            int s = (warp << 5) + i;
            const float2* gps = reinterpret_cast<const float2*>(s_gp + s * 24);
            float ax = 0.f, ay = 0.f, az = 0.f, aw = 0.f;
            #pragma unroll
            for (int p = 0; p < 3; p++) {
                float2 pw = gps[p * 4 + corner];
                int off = __float_as_int(pw.x);
                float w = pw.y;
                float4 vv = __ldg(reinterpret_cast<const float4*>(g_planesT + off) + chunk);
                ax = fmaf(vv.x, w, ax);
                ay = fmaf(vv.y, w, ay);
                az = fmaf(vv.z, w, az);
                aw = fmaf(vv.w, w, aw);
            }
            const unsigned FULL = 0xffffffffu;
            ax += __shfl_xor_sync(FULL, ax, 8);
            ay += __shfl_xor_sync(FULL, ay, 8);
            az += __shfl_xor_sync(FULL, az, 8);
            aw += __shfl_xor_sync(FULL, aw, 8);
            ax += __shfl_xor_sync(FULL, ax, 16);
            ay += __shfl_xor_sync(FULL, ay, 16);
            az += __shfl_xor_sync(FULL, az, 16);
            aw += __shfl_xor_sync(FULL, aw, 16);
            if (lane < 8) {
                const float k3 = 1.f / 3.f;
                *reinterpret_cast<float4*>(s_buf + s * BUFS + chunk * 4) =
                    make_float4(ax * k3, ay * k3, az * k3, aw * k3);
            }
        }
    }
    __syncwarp();

    // ---- layer 1: C1[192x64] = feat[192x32] x W1[32x64] (tf32, 3-term) ----
    float c1[2][8][4] = {};
    #pragma unroll
    for (int mt = 0; mt < 2; mt++) {
        unsigned ah[4][4], al[4][4];
        int r0 = warp * 32 + mt * 16 + g;
        #pragma unroll
        for (int kt = 0; kt < 4; kt++) {
            int cb = kt * 8 + t;
            split_tf(s_buf[r0 * BUFS + cb], ah[kt][0], al[kt][0]);
            split_tf(s_buf[(r0 + 8) * BUFS + cb], ah[kt][1], al[kt][1]);
            split_tf(s_buf[r0 * BUFS + cb + 4], ah[kt][2], al[kt][2]);
            split_tf(s_buf[(r0 + 8) * BUFS + cb + 4], ah[kt][3], al[kt][3]);
        }
        #pragma unroll
        for (int nt = 0; nt < 8; nt++) {
            #pragma unroll
            for (int kt = 0; kt < 4; kt++) {
                uint2 bh = *reinterpret_cast<const uint2*>(w1f + ((nt * 4 + kt) * 32 + lane) * 2);
                uint2 bl = *reinterpret_cast<const uint2*>(w1f + 2048 + ((nt * 4 + kt) * 32 + lane) * 2);
                mma8(c1[mt][nt], ah[kt], bh.x, bh.y);
                mma8(c1[mt][nt], al[kt], bh.x, bh.y);
                mma8(c1[mt][nt], ah[kt], bl.x, bl.y);
            }
        }
    }
    __syncwarp();

    // ---- softplus + bias, store h into s_buf (overwrites feat, own rows) ----
    #pragma unroll
    for (int mt = 0; mt < 2; mt++) {
        int row = warp * 32 + mt * 16 + g;
        #pragma unroll
        for (int nt = 0; nt < 8; nt++) {
            int col = nt * 8 + t * 2;
            float ba = s_b1[col], bb2 = s_b1[col + 1];
            float h0 = softplus_f(c1[mt][nt][0] + ba);
            float h1 = softplus_f(c1[mt][nt][1] + bb2);
            float h2 = softplus_f(c1[mt][nt][2] + ba);
            float h3 = softplus_f(c1[mt][nt][3] + bb2);
            *reinterpret_cast<float2*>(s_buf + row * BUFS + col) = make_float2(h0, h1);
            *reinterpret_cast<float2*>(s_buf + (row + 8) * BUFS + col) = make_float2(h2, h3);
        }
    }
    __syncwarp();

    // ---- layer 2: C2[192x40] = h[192x64] x W2[64x40] ----
    float c2[2][5][4] = {};
    #pragma unroll
    for (int mt = 0; mt < 2; mt++) {
        unsigned ah[8][4], al[8][4];
        int r0 = warp * 32 + mt * 16 + g;
        #pragma unroll
        for (int kt = 0; kt < 8; kt++) {
            int cb = kt * 8 + t;
            split_tf(s_buf[r0 * BUFS + cb], ah[kt][0], al[kt][0]);
            split_tf(s_buf[(r0 + 8) * BUFS + cb], ah[kt][1], al[kt][1]);
            split_tf(s_buf[r0 * BUFS + cb + 4], ah[kt][2], al[kt][2]);
            split_tf(s_buf[(r0 + 8) * BUFS + cb + 4], ah[kt][3], al[kt][3]);
        }
        #pragma unroll
        for (int nt = 0; nt < 5; nt++) {
            #pragma unroll
            for (int kt = 0; kt < 8; kt++) {
                uint2 bh = *reinterpret_cast<const uint2*>(w2f + ((nt * 8 + kt) * 32 + lane) * 2);
                uint2 bl = *reinterpret_cast<const uint2*>(w2f + 2560 + ((nt * 8 + kt) * 32 + lane) * 2);
                mma8(c2[mt][nt], ah[kt], bh.x, bh.y);
                mma8(c2[mt][nt], al[kt], bh.x, bh.y);
                mma8(c2[mt][nt], ah[kt], bl.x, bl.y);
            }
        }
    }
    __syncwarp();

    // ---- epilogue: sigma -> s_sig (+sdf out on PASS0), rgb -> s_buf cols 0..31
    #pragma unroll
    for (int mt = 0; mt < 2; mt++) {
        int rowA = warp * 32 + mt * 16 + g;
        int rowB = rowA + 8;
        #pragma unroll
        for (int nt = 0; nt < 5; nt++) {
            int colA = nt * 8 + t * 2;
            int colB = colA + 1;
            float v0 = c2[mt][nt][0], v1 = c2[mt][nt][1];
            float v2 = c2[mt][nt][2], v3 = c2[mt][nt][3];
            if (nt == 0 && t == 0) {
                float sA = v0 + s_b2[0];
                float sB = v2 + s_b2[0];
                s_sig[rowA] = sA;
                s_sig[rowB] = sB;
                if (PASS == 0) {
                    out[OFF_SDF + blockIdx.x * 192 + rowA] = sA;
                    out[OFF_SDF + blockIdx.x * 192 + rowB] = sB;
                }
            } else if (colA < 33) {
                s_buf[rowA * BUFS + colA - 1] = sigmoid_f(v0 + s_b2[colA]) * 1.002f - 0.001f;
                s_buf[rowB * BUFS + colA - 1] = sigmoid_f(v2 + s_b2[colA]) * 1.002f - 0.001f;
            }
            if (colB < 33) {
                s_buf[rowA * BUFS + colB - 1] = sigmoid_f(v1 + s_b2[colB]) * 1.002f - 0.001f;
                s_buf[rowB * BUFS + colB - 1] = sigmoid_f(v3 + s_b2[colB]) * 1.002f - 0.001f;
            }
        }
    }
    __syncthreads();

    if (PASS == 0) {
        // coalesced rgb_c store
        size_t ob = (size_t)blockIdx.x * 192 * CRGB;
        for (int i = tid; i < 192 * CRGB; i += 192) {
            int sm = i >> 5, k = i & 31;
            g_rgb_c[ob + i] = s_buf[sm * BUFS + k];
        }
        // fused importance sampling: thread r handles ray r
        if (tid < 4) {
            const float* sg = s_sig + tid * SC;
            int rayO = blockIdx.x * 4 + tid;
            float w[SC - 1];
            float T = 1.f;
            float prev = sg[0];
            for (int i = 0; i < SC - 1; i++) {
                float cur = sg[i + 1];
                float dens = softplus_f(0.5f * (prev + cur) - 1.f);
                float a = 1.f - __expf(-dens * DELTA_F);
                w[i] = a * T;
                T *= (1.f - a + 1e-10f);
                prev = cur;
            }
            float pw[45];
            float sum = 0.f;
            for (int i = 1; i <= 45; i++) {
                float wp_i = w[i - 1];
                float wp_i1 = w[i];
                float wp_i2 = (i + 2 <= 47) ? w[i + 1] : 0.f;
                float wm0 = fmaxf(wp_i, wp_i1);
                float wm1 = fmaxf(wp_i1, wp_i2);
                float val = 0.5f * (wm0 + wm1) + 0.01f;
                pw[i - 1] = val;
                sum += val;
            }
            float cdf[46];
            cdf[0] = 0.f;
            for (int i = 0; i < 45; i++) cdf[i + 1] = cdf[i] + pw[i] / sum;
            int idx = 0;
            for (int j = 0; j < SF; j++) {
                float u = (float)j / 47.0f;
                while (idx < 46 && cdf[idx] <= u) idx++;
                int below = idx - 1;
                below = below < 0 ? 0 : (below > 45 ? 45 : below);
                int above = idx > 45 ? 45 : idx;
                float cb = cdf[below], ca = cdf[above];
                float bbv = 0.5f * (zc_depth(below) + zc_depth(below + 1));
                float bav = 0.5f * (zc_depth(above) + zc_depth(above + 1));
                float d = ca - cb;
                float denom = (d < 1e-5f) ? 1.f : d;
                g_zf[(size_t)rayO * SF + j] = bbv + (u - cb) / denom * (bav - bbv);
            }
        }
    } else {
        // fused merge + final ray march: warp wr (<4) handles ray wr
        if (warp < 4) {
            int rayO = blockIdx.x * 4 + warp;
            const float* sdfc = out + OFF_SDF + (size_t)rayO * SC;
            const float* zf = s_z + warp * SF;
            const float* sf = s_sig + warp * SF;
            int ic = 0, ifn = 0;
            float T = 1.f, rgb_acc = 0.f, dep = 0.f, ws = 0.f;
            float zp, sp2, cp;
            {
                bool tc = (zc_depth(0) <= zf[0]);
                if (tc) {
                    zp = zc_depth(0); sp2 = __ldg(&sdfc[0]);
                    cp = __ldg(&g_rgb_c[((size_t)rayO * SC) * CRGB + lane]);
                    ic = 1;
                } else {
                    zp = zf[0]; sp2 = sf[0];
                    cp = s_buf[(warp * SF) * BUFS + lane];
                    ifn = 1;
                }
            }
            for (int i = 1; i < SC + SF; i++) {
                bool tc = (ic < SC) && (ifn >= SF || zc_depth(ic) <= zf[ifn]);
                float z, sgv, cc;
                if (tc) {
                    z = zc_depth(ic); sgv = __ldg(&sdfc[ic]);
                    cc = __ldg(&g_rgb_c[((size_t)rayO * SC + ic) * CRGB + lane]);
                    ic++;
                } else {
                    z = zf[ifn]; sgv = sf[ifn];
                    cc = s_buf[(warp * SF + ifn) * BUFS + lane];
                    ifn++;
                }
                float delta = z - zp;
                float cmid = 0.5f * (cp + cc);
                float smid = softplus_f(0.5f * (sp2 + sgv) - 1.f);
                float a = 1.f - __expf(-smid * delta);
                float wgt = a * T;
                T *= (1.f - a + 1e-10f);
                rgb_acc = fmaf(wgt, cmid, rgb_acc);
                dep = fmaf(wgt, 0.5f * (zp + z), dep);
                ws += wgt;
                zp = z; sp2 = sgv; cp = cc;
            }
            out[(size_t)rayO * CRGB + lane] = rgb_acc * 2.f - 1.f;
            if (lane == 0) {
                out[OFF_DEPTH + rayO] = dep;
                out[OFF_WSUM + rayO] = ws;
            }
        }
    }
}

// ---------------------------------------------------------------------------
extern "C" void kernel_launch(void* const* d_in, const int* in_sizes, int n_in,
                              void* d_out, int out_size) {
    const float* planes = (const float*)d_in[0];
    const float* org    = (const float*)d_in[1];
    const float* dir    = (const float*)d_in[2];
    const float* w1     = (const float*)d_in[3];
    const float* b1     = (const float*)d_in[4];
    const float* w2     = (const float*)d_in[5];
    const float* b2     = (const float*)d_in[6];
    float* out = (float*)d_out;

    const int smem_bytes = SM_TOTALF * sizeof(float);
    cudaFuncSetAttribute(eval_kernel<0>, cudaFuncAttributeMaxDynamicSharedMemorySize, smem_bytes);
    cudaFuncSetAttribute(eval_kernel<1>, cudaFuncAttributeMaxDynamicSharedMemorySize, smem_bytes);

    {
        dim3 tb(32, 8), tg(HPX * HPX / 32, 6);
        transpose_planes_kernel<<<tg, tb>>>(planes);
    }
    eval_kernel<0><<<NRAY / 4, 192, smem_bytes>>>(org, dir, w1, b1, w2, b2, out);
    eval_kernel<1><<<NRAY / 4, 192, smem_bytes>>>(org, dir, w1, b1, w2, b2, out);
}

// round 10
// speedup vs baseline: 1.9607x; 1.9607x over previous
#include <cuda_runtime.h>
#include <math.h>
#include <stdint.h>

// ---------------------------------------------------------------------------
// ImportanceRenderer: scalar-free gather (smem params) + packed f32x2 MLP.
//  K0: transpose planes (B,3,32,256,256) -> channel-last
//  K1: coarse eval + fused importance sampling
//  K2: fine eval + fused merge + final 96-sample ray march
// Block = 192 threads = 6 warps = 4 rays x 48 samples.
// ---------------------------------------------------------------------------

#define B_N 2
#define R_N 4096
#define SC 48
#define SF 48
#define NRAY (B_N * R_N)        // 8192
#define NSAMP (NRAY * SC)       // 393216
#define CPL 32
#define HPX 256
#define HID 64
#define CRGB 32
#define PLSTRIDE (HPX * HPX * CPL)

#define RAY_START_F 2.25f
#define DELTA_F (1.05f / 47.0f)

#define OFF_DEPTH (NRAY * CRGB)         // 262144
#define OFF_WSUM  (OFF_DEPTH + NRAY)    // 270336
#define OFF_SDF   (OFF_WSUM + NRAY)     // 278528

#define BUFS 40   // s_buf row stride (40*4=160B, 16B aligned per row)

// Dynamic smem layout (float offsets); every region 16B aligned
#define SM_BUF   0                      // 192*40 = 7680
#define SM_GP    7680                   // 192*24 = 4608
#define SM_W1P   12288                  // 64*32  = 2048 (w1 packed, j-major)
#define SM_W2P   14336                  // 64*40  = 2560 (w2 packed, j-major, padded)
#define SM_B1    16896                  // 64
#define SM_B2    16960                  // 36 (16B aligned: 16960*4 % 16 == 0)
#define SM_SIG   16996                  // 192
#define SM_Z     17188                  // 192
#define SM_TOTALF 17380                 // 69520 bytes

// Static scratch
__device__ float g_planesT[6 * PLSTRIDE];           // 50.3 MB
__device__ float g_rgb_c[(size_t)NSAMP * CRGB];     // 50.3 MB
__device__ float g_zf[NSAMP];

typedef unsigned long long ull;

__device__ __forceinline__ float softplus_f(float x) {
    return fmaxf(x, 0.f) + __logf(1.f + __expf(-fabsf(x)));
}
__device__ __forceinline__ float sigmoid_f(float x) {
    return 1.f / (1.f + __expf(-x));
}
__device__ __forceinline__ float zc_depth(int i) {
    return RAY_START_F + ((float)i + 0.5f) * DELTA_F;
}
// ---- Blackwell packed fp32x2 ops (SASS FFMA2/FMUL2/FADD2) ----
__device__ __forceinline__ ull fma2(ull a, ull b, ull c) {
    ull d;
    asm("fma.rn.f32x2 %0, %1, %2, %3;" : "=l"(d) : "l"(a), "l"(b), "l"(c));
    return d;
}
__device__ __forceinline__ ull add2(ull a, ull b) {
    ull d;
    asm("add.rn.f32x2 %0, %1, %2;" : "=l"(d) : "l"(a), "l"(b));
    return d;
}
__device__ __forceinline__ ull mul2(ull a, ull b) {
    ull d;
    asm("mul.rn.f32x2 %0, %1, %2;" : "=l"(d) : "l"(a), "l"(b));
    return d;
}
__device__ __forceinline__ ull pk2(float lo, float hi) {
    ull r;
    asm("mov.b64 %0, {%1,%2};" : "=l"(r) : "f"(lo), "f"(hi));
    return r;
}
__device__ __forceinline__ void upk2(ull v, float& lo, float& hi) {
    asm("mov.b64 {%0,%1}, %2;" : "=f"(lo), "=f"(hi) : "l"(v));
}

// ---------------------------------------------------------------------------
// K0: tiled transpose per plane
// ---------------------------------------------------------------------------
__global__ void transpose_planes_kernel(const float* __restrict__ in) {
    __shared__ float tile[32][33];
    int p = blockIdx.y;
    int hw0 = blockIdx.x * 32;
    int tx = threadIdx.x, ty = threadIdx.y;
    const float* ip = in + (size_t)p * CPL * (HPX * HPX);
    float* op = g_planesT + (size_t)p * PLSTRIDE;
    #pragma unroll
    for (int c = ty; c < 32; c += 8)
        tile[c][tx] = ip[(size_t)c * (HPX * HPX) + hw0 + tx];
    __syncthreads();
    #pragma unroll
    for (int r = ty; r < 32; r += 8)
        op[(size_t)(hw0 + r) * 32 + tx] = tile[tx][r];
}

// ---------------------------------------------------------------------------
// K1/K2 fused eval
// ---------------------------------------------------------------------------
template <int PASS>
__global__ __launch_bounds__(192, 3)
void eval_kernel(const float* __restrict__ origins,
                 const float* __restrict__ dirs,
                 const float* __restrict__ w1, const float* __restrict__ b1,
                 const float* __restrict__ w2, const float* __restrict__ b2,
                 float* __restrict__ out) {
    extern __shared__ float smem[];
    float* s_buf = smem + SM_BUF;
    float* s_gp  = smem + SM_GP;
    float* s_w1p = smem + SM_W1P;
    float* s_w2p = smem + SM_W2P;
    float* s_b1  = smem + SM_B1;
    float* s_b2  = smem + SM_B2;
    float* s_sig = smem + SM_SIG;
    float* s_z   = smem + SM_Z;

    const int tid = threadIdx.x;
    const int lane = tid & 31;
    const int warp = tid >> 5;
    const unsigned FULL = 0xffffffffu;

    // ---- weight prep: w1 packed j-major (pairs along c), w2 padded j-major ----
    for (int i = tid; i < HID * CPL; i += 192) {
        int j = i >> 5, c = i & 31;
        s_w1p[i] = w1[c * HID + j];
    }
    for (int i = tid; i < HID * 40; i += 192) {
        int j = i / 40, k = i - j * 40;
        s_w2p[i] = (k < 33) ? w2[j * 33 + k] : 0.f;
    }
    if (tid < HID) s_b1[tid] = b1[tid];
    if (tid < 36) s_b2[tid] = (tid < 33) ? b2[tid] : 0.f;

    // ---- phase A: per-sample coords -> 12 (offset,weight) corner params ----
    const int gs = blockIdx.x * 192 + tid;
    const int rayLocal = tid / 48;
    const int samp = tid - rayLocal * 48;
    const int ray = blockIdx.x * 4 + rayLocal;

    float tz;
    if (PASS == 0) tz = zc_depth(samp);
    else tz = __ldg(&g_zf[gs]);
    s_z[tid] = tz;

    {
        float ox = __ldg(&origins[ray * 3 + 0]);
        float oy = __ldg(&origins[ray * 3 + 1]);
        float oz = __ldg(&origins[ray * 3 + 2]);
        float dx = __ldg(&dirs[ray * 3 + 0]);
        float dy = __ldg(&dirs[ray * 3 + 1]);
        float dz = __ldg(&dirs[ray * 3 + 2]);
        float X = fmaf(tz, dx, ox), Y = fmaf(tz, dy, oy), Z = fmaf(tz, dz, oz);
        int bb = ray >> 12;
        #pragma unroll
        for (int p = 0; p < 3; p++) {
            float u = (p == 2) ? Z : X;
            float v = (p == 0) ? Y : (p == 1) ? Z : X;
            float x = fmaf(u, 128.f, 127.5f);
            float y = fmaf(v, 128.f, 127.5f);
            float x0f = floorf(x), y0f = floorf(y);
            float fx = x - x0f, fy = y - y0f;
            int xi0 = min(max((int)x0f, 0), 255);
            int xi1 = min(max((int)x0f + 1, 0), 255);
            int yi0 = min(max((int)y0f, 0), 255);
            int yi1 = min(max((int)y0f + 1, 0), 255);
            float wx0 = (x0f >= 0.f && x0f < 256.f) ? (1.f - fx) : 0.f;
            float wx1 = (x0f + 1.f >= 0.f && x0f + 1.f < 256.f) ? fx : 0.f;
            float wy0 = (y0f >= 0.f && y0f < 256.f) ? (1.f - fy) : 0.f;
            float wy1 = (y0f + 1.f >= 0.f && y0f + 1.f < 256.f) ? fy : 0.f;
            int base = (bb * 3 + p) * PLSTRIDE;
            int o0 = base + yi0 * (HPX * CPL);
            int o1 = base + yi1 * (HPX * CPL);
            float2* gp = reinterpret_cast<float2*>(s_gp + tid * 24 + p * 8);
            gp[0] = make_float2(__int_as_float(o0 + xi0 * CPL), wy0 * wx0);
            gp[1] = make_float2(__int_as_float(o0 + xi1 * CPL), wy0 * wx1);
            gp[2] = make_float2(__int_as_float(o1 + xi0 * CPL), wy1 * wx0);
            gp[3] = make_float2(__int_as_float(o1 + xi1 * CPL), wy1 * wx1);
        }
    }
    __syncthreads();

    // ---- gather: warp-cooperative, lane = corner(2b) x chunk(3b), packed ----
    {
        const int corner = lane >> 3;
        const int chunk = lane & 7;
        const ull k3p = pk2(1.f / 3.f, 1.f / 3.f);
        for (int i = 0; i < 32; i++) {
            int s = (warp << 5) + i;
            ull a0 = 0ull, a1 = 0ull;
            #pragma unroll
            for (int p = 0; p < 3; p++) {
                float2 pw = *reinterpret_cast<const float2*>(
                    s_gp + s * 24 + p * 8 + corner * 2);
                int off = __float_as_int(pw.x);
                ull wpk = pk2(pw.y, pw.y);
                ulonglong2 v = __ldg(
                    reinterpret_cast<const ulonglong2*>(g_planesT + off) + chunk);
                a0 = fma2(v.x, wpk, a0);
                a1 = fma2(v.y, wpk, a1);
            }
            a0 = add2(a0, __shfl_xor_sync(FULL, a0, 8));
            a1 = add2(a1, __shfl_xor_sync(FULL, a1, 8));
            a0 = add2(a0, __shfl_xor_sync(FULL, a0, 16));
            a1 = add2(a1, __shfl_xor_sync(FULL, a1, 16));
            if (lane < 8) {
                ulonglong2 r;
                r.x = mul2(a0, k3p);
                r.y = mul2(a1, k3p);
                *reinterpret_cast<ulonglong2*>(s_buf + s * BUFS + chunk * 4) = r;
            }
        }
    }
    __syncwarp();

    // ---- MLP: thread = sample; packed f32x2 everywhere ----
    ull feat2[16];
    {
        const ulonglong2* f4 = reinterpret_cast<const ulonglong2*>(s_buf + tid * BUFS);
        #pragma unroll
        for (int k = 0; k < 8; k++) {
            ulonglong2 v = f4[k];
            feat2[2 * k] = v.x;
            feat2[2 * k + 1] = v.y;
        }
    }
    ull acc2[18];
    {
        const ulonglong2* b2p = reinterpret_cast<const ulonglong2*>(s_b2);
        #pragma unroll
        for (int kk = 0; kk < 9; kk++) {
            ulonglong2 v = b2p[kk];
            acc2[2 * kk] = v.x;
            acc2[2 * kk + 1] = v.y;
        }
    }
    {
        const ulonglong2* w1p4 = reinterpret_cast<const ulonglong2*>(s_w1p);
        const ulonglong2* w2p4 = reinterpret_cast<const ulonglong2*>(s_w2p);
        #pragma unroll 2
        for (int j = 0; j < HID; j++) {
            ull h0 = 0ull, h1 = 0ull;
            #pragma unroll
            for (int i2 = 0; i2 < 8; i2++) {
                ulonglong2 w = w1p4[j * 8 + i2];
                h0 = fma2(feat2[2 * i2], w.x, h0);
                h1 = fma2(feat2[2 * i2 + 1], w.y, h1);
            }
            float l0, u0, l1, u1;
            upk2(h0, l0, u0);
            upk2(h1, l1, u1);
            float h = softplus_f((l0 + u0) + (l1 + u1) + s_b1[j]);
            ull hp = pk2(h, h);
            #pragma unroll
            for (int kk = 0; kk < 9; kk++) {
                ulonglong2 w = w2p4[j * 10 + kk];
                acc2[2 * kk] = fma2(hp, w.x, acc2[2 * kk]);
                acc2[2 * kk + 1] = fma2(hp, w.y, acc2[2 * kk + 1]);
            }
        }
    }
    // ---- epilogue: sigma + rgb ----
    // acc2[m] = packed (o[2m], o[2m+1]); o[0]=sigma, o[1..32]=rgb, o[33..]=pad
    {
        float o0, o1;
        upk2(acc2[0], o0, o1);
        s_sig[tid] = o0;
        if (PASS == 0) out[OFF_SDF + gs] = o0;
        s_buf[tid * BUFS + 0] = sigmoid_f(o1) * 1.002f - 0.001f;   // rgb0 = o[1]
        #pragma unroll
        for (int k2 = 1; k2 <= 16; k2++) {
            float lo, hi;
            upk2(acc2[k2], lo, hi);
            // lo = o[2*k2] -> rgb index 2*k2-1
            s_buf[tid * BUFS + 2 * k2 - 1] = sigmoid_f(lo) * 1.002f - 0.001f;
            // hi = o[2*k2+1] -> rgb index 2*k2 (k2==16 -> o[33] is padding; skip)
            if (k2 < 16)
                s_buf[tid * BUFS + 2 * k2] = sigmoid_f(hi) * 1.002f - 0.001f;
        }
    }
    __syncthreads();

    if (PASS == 0) {
        // coalesced rgb_c store
        size_t ob = (size_t)blockIdx.x * 192 * CRGB;
        for (int i = tid; i < 192 * CRGB; i += 192) {
            int sm = i >> 5, k = i & 31;
            g_rgb_c[ob + i] = s_buf[sm * BUFS + k];
        }
        // fused importance sampling: thread r handles ray r
        if (tid < 4) {
            const float* sg = s_sig + tid * SC;
            int rayO = blockIdx.x * 4 + tid;
            float w[SC - 1];
            float T = 1.f;
            float prev = sg[0];
            for (int i = 0; i < SC - 1; i++) {
                float cur = sg[i + 1];
                float dens = softplus_f(0.5f * (prev + cur) - 1.f);
                float a = 1.f - __expf(-dens * DELTA_F);
                w[i] = a * T;
                T *= (1.f - a + 1e-10f);
                prev = cur;
            }
            float pw[45];
            float sum = 0.f;
            for (int i = 1; i <= 45; i++) {
                float wp_i = w[i - 1];
                float wp_i1 = w[i];
                float wp_i2 = (i + 2 <= 47) ? w[i + 1] : 0.f;
                float wm0 = fmaxf(wp_i, wp_i1);
                float wm1 = fmaxf(wp_i1, wp_i2);
                float val = 0.5f * (wm0 + wm1) + 0.01f;
                pw[i - 1] = val;
                sum += val;
            }
            float cdf[46];
            cdf[0] = 0.f;
            for (int i = 0; i < 45; i++) cdf[i + 1] = cdf[i] + pw[i] / sum;
            int idx = 0;
            for (int j = 0; j < SF; j++) {
                float u = (float)j / 47.0f;
                while (idx < 46 && cdf[idx] <= u) idx++;
                int below = idx - 1;
                below = below < 0 ? 0 : (below > 45 ? 45 : below);
                int above = idx > 45 ? 45 : idx;
                float cb = cdf[below], ca = cdf[above];
                float bbv = 0.5f * (zc_depth(below) + zc_depth(below + 1));
                float bav = 0.5f * (zc_depth(above) + zc_depth(above + 1));
                float d = ca - cb;
                float denom = (d < 1e-5f) ? 1.f : d;
                g_zf[(size_t)rayO * SF + j] = bbv + (u - cb) / denom * (bav - bbv);
            }
        }
    } else {
        // fused merge + final ray march: warp wr (<4) handles ray wr
        if (warp < 4) {
            int rayO = blockIdx.x * 4 + warp;
            const float* sdfc = out + OFF_SDF + (size_t)rayO * SC;
            const float* zf = s_z + warp * SF;
            const float* sf = s_sig + warp * SF;
            int ic = 0, ifn = 0;
            float T = 1.f, rgb_acc = 0.f, dep = 0.f, ws = 0.f;
            float zp, sp2, cp;
            {
                bool tc = (zc_depth(0) <= zf[0]);
                if (tc) {
                    zp = zc_depth(0); sp2 = __ldg(&sdfc[0]);
                    cp = __ldg(&g_rgb_c[((size_t)rayO * SC) * CRGB + lane]);
                    ic = 1;
                } else {
                    zp = zf[0]; sp2 = sf[0];
                    cp = s_buf[(warp * SF) * BUFS + lane];
                    ifn = 1;
                }
            }
            for (int i = 1; i < SC + SF; i++) {
                bool tc = (ic < SC) && (ifn >= SF || zc_depth(ic) <= zf[ifn]);
                float z, sgv, cc;
                if (tc) {
                    z = zc_depth(ic); sgv = __ldg(&sdfc[ic]);
                    cc = __ldg(&g_rgb_c[((size_t)rayO * SC + ic) * CRGB + lane]);
                    ic++;
                } else {
                    z = zf[ifn]; sgv = sf[ifn];
                    cc = s_buf[(warp * SF + ifn) * BUFS + lane];
                    ifn++;
                }
                float delta = z - zp;
                float cmid = 0.5f * (cp + cc);
                float smid = softplus_f(0.5f * (sp2 + sgv) - 1.f);
                float a = 1.f - __expf(-smid * delta);
                float wgt = a * T;
                T *= (1.f - a + 1e-10f);
                rgb_acc = fmaf(wgt, cmid, rgb_acc);
                dep = fmaf(wgt, 0.5f * (zp + z), dep);
                ws += wgt;
                zp = z; sp2 = sgv; cp = cc;
            }
            out[(size_t)rayO * CRGB + lane] = rgb_acc * 2.f - 1.f;
            if (lane == 0) {
                out[OFF_DEPTH + rayO] = dep;
                out[OFF_WSUM + rayO] = ws;
            }
        }
    }
}

// ---------------------------------------------------------------------------
extern "C" void kernel_launch(void* const* d_in, const int* in_sizes, int n_in,
                              void* d_out, int out_size) {
    const float* planes = (const float*)d_in[0];
    const float* org    = (const float*)d_in[1];
    const float* dir    = (const float*)d_in[2];
    const float* w1     = (const float*)d_in[3];
    const float* b1     = (const float*)d_in[4];
    const float* w2     = (const float*)d_in[5];
    const float* b2     = (const float*)d_in[6];
    float* out = (float*)d_out;

    const int smem_bytes = SM_TOTALF * sizeof(float);
    cudaFuncSetAttribute(eval_kernel<0>, cudaFuncAttributeMaxDynamicSharedMemorySize, smem_bytes);
    cudaFuncSetAttribute(eval_kernel<1>, cudaFuncAttributeMaxDynamicSharedMemorySize, smem_bytes);

    {
        dim3 tb(32, 8), tg(HPX * HPX / 32, 6);
        transpose_planes_kernel<<<tg, tb>>>(planes);
    }
    eval_kernel<0><<<NRAY / 4, 192, smem_bytes>>>(org, dir, w1, b1, w2, b2, out);
    eval_kernel<1><<<NRAY / 4, 192, smem_bytes>>>(org, dir, w1, b1, w2, b2, out);
}